// round 11
// baseline (speedup 1.0000x reference)
#include <cuda_runtime.h>
#include <cuda_fp16.h>
#include <math.h>
#include <stdint.h>

#define S_LEN 4096
#define NBATCH 4
#define DIM 256
#define M_TOTAL (NBATCH * S_LEN)
#define KVT 64
#define NITER (S_LEN / KVT)
#define LOG2E 1.4426950408889634f

// ---------------- scratch globals (fp16 precomputed operands) ----------------
__device__ __half g_Qh[M_TOTAL * DIM];              // row-major, pre-scaled log2e/16
__device__ __half g_Kh[M_TOTAL * DIM];              // row-major
__device__ __half g_VTh[NBATCH * DIM * S_LEN];      // [b][d][s]
__device__ float4 g_cs[S_LEN];                      // (cos0,sin0,cos1,sin1)

// ---------------- low-level helpers ----------------
__device__ __forceinline__ uint32_t smem_u32(const void* p) {
    uint32_t a;
    asm("{ .reg .u64 t; cvta.to.shared.u64 t, %1; cvt.u32.u64 %0, t; }" : "=r"(a) : "l"(p));
    return a;
}
__device__ __forceinline__ void ldsm4(uint32_t& r0, uint32_t& r1, uint32_t& r2, uint32_t& r3,
                                      uint32_t addr) {
    asm volatile("ldmatrix.sync.aligned.m8n8.x4.shared.b16 {%0,%1,%2,%3}, [%4];"
                 : "=r"(r0), "=r"(r1), "=r"(r2), "=r"(r3) : "r"(addr));
}
__device__ __forceinline__ void mma16816(float* d, const uint32_t* a, const uint32_t* b) {
    asm volatile("mma.sync.aligned.m16n8k16.row.col.f32.f16.f16.f32 "
                 "{%0,%1,%2,%3}, {%4,%5,%6,%7}, {%8,%9}, {%0,%1,%2,%3};"
                 : "+f"(d[0]), "+f"(d[1]), "+f"(d[2]), "+f"(d[3])
                 : "r"(a[0]), "r"(a[1]), "r"(a[2]), "r"(a[3]), "r"(b[0]), "r"(b[1]));
}
__device__ __forceinline__ uint32_t pk2(float x, float y) {
    __half2 h = __floats2half2_rn(x, y);
    return reinterpret_cast<uint32_t&>(h);
}
__device__ __forceinline__ float ex2f(float x) {
    float y; asm("ex2.approx.ftz.f32 %0, %1;" : "=f"(y) : "f"(x)); return y;
}
#define CP16(dst, src) \
    asm volatile("cp.async.cg.shared.global [%0], [%1], 16;" :: "r"(dst), "l"(src))
#define CP_COMMIT() asm volatile("cp.async.commit_group;" ::: "memory")
#define CP_WAIT0()  asm volatile("cp.async.wait_group 0;" ::: "memory")

// ---------------------------------------------------------------------------
__global__ void cs_kernel() {
    int p = blockIdx.x * blockDim.x + threadIdx.x;
    if (p < S_LEN) {
        float s0, c0, s1, c1;
        sincospif((float)(p % 24) * (1.0f / 12.0f), &s0, &c0);
        sincospif((float)(p % 720) * (1.0f / 360.0f), &s1, &c1);
        g_cs[p] = make_float4(c0, s0, c1, s1);
    }
}

// no-op spacer: keeps attn in ncu's -s 5 -c 1 capture window
__global__ void probe_kernel() {}

// ---------------------------------------------------------------------------
// QKV projection on HMMA, plain fp16 operands.
// ---------------------------------------------------------------------------
#define QK_BIAS 0
#define QK_XH 512
#define QK_WH 9728
#define QK_SMEM (43776 * 2)
#define P_TR 266

__global__ __launch_bounds__(256, 1) void qkv_kernel(
    const float* __restrict__ x,
    const float* __restrict__ Wq, const float* __restrict__ bq,
    const float* __restrict__ Wk, const float* __restrict__ bk,
    const float* __restrict__ Wv, const float* __restrict__ bv)
{
    extern __shared__ __align__(16) __half smq[];
    const float* W; const float* bias;
    int z = blockIdx.z;
    if (z == 0)      { W = Wq; bias = bq; }
    else if (z == 1) { W = Wk; bias = bk; }
    else             { W = Wv; bias = bv; }

    uint32_t uS = smem_u32(smq);
    int tid = threadIdx.x;
    int lane = tid & 31, wid = tid >> 5;
    int g = lane >> 2, tig = lane & 3;
    int l7 = lane & 7, bit3 = (lane >> 3) & 1, bit4 = (lane >> 4) & 1;
    int warp_m = wid * 16;
    int m0 = blockIdx.x * 128;

    float* biasS = (float*)(smq + QK_BIAS);
    if (tid < 256) biasS[tid] = bias[tid];

    uint32_t xa_h = uS + (uint32_t)(QK_XH + (warp_m + l7 + bit3 * 8) * 72 + bit4 * 8) * 2;
    uint32_t wb_h = uS + (uint32_t)(QK_WH + (l7 + bit4 * 8) * 72 + bit3 * 8) * 2;

    float y[128];
    #pragma unroll
    for (int i = 0; i < 128; i++) y[i] = 0.0f;

    #pragma unroll 1
    for (int k0 = 0; k0 < DIM; k0 += 64) {
        __syncthreads();
        for (int f = tid; f < 2048; f += 256) {
            int r = f >> 4, c = (f & 15) * 4;
            float4 v = *(const float4*)(x + (size_t)(m0 + r) * DIM + k0 + c);
            *(__half2*)&smq[QK_XH + r * 72 + c]     = __floats2half2_rn(v.x, v.y);
            *(__half2*)&smq[QK_XH + r * 72 + c + 2] = __floats2half2_rn(v.z, v.w);
        }
        for (int f = tid; f < 4096; f += 256) {
            int r = f >> 4, c = (f & 15) * 4;
            float4 v = *(const float4*)(W + (size_t)r * DIM + k0 + c);
            *(__half2*)&smq[QK_WH + r * 72 + c]     = __floats2half2_rn(v.x, v.y);
            *(__half2*)&smq[QK_WH + r * 72 + c + 2] = __floats2half2_rn(v.z, v.w);
        }
        __syncthreads();

        #pragma unroll
        for (int ks = 0; ks < 4; ks++) {
            uint32_t ah[4];
            ldsm4(ah[0], ah[1], ah[2], ah[3], xa_h + ks * 32);
            #pragma unroll
            for (int j2 = 0; j2 < 16; j2++) {
                uint32_t bh[4];
                ldsm4(bh[0], bh[1], bh[2], bh[3], wb_h + j2 * 2304 + ks * 32);
                mma16816(&y[(j2 * 2) * 4],     ah, &bh[0]);
                mma16816(&y[(j2 * 2 + 1) * 4], ah, &bh[2]);
            }
        }
    }

    if (z < 2) {
        float scale = (z == 0) ? (LOG2E / 16.0f) : 1.0f;
        __half* dst = ((z == 0) ? g_Qh : g_Kh);
        __half* rowA = dst + (size_t)(m0 + warp_m + g) * DIM;
        __half* rowB = rowA + 8 * DIM;
        #pragma unroll
        for (int jt = 0; jt < 32; jt++) {
            int n = jt * 8 + tig * 2;
            *(__half2*)(rowA + n) = __floats2half2_rn((y[jt*4+0] + biasS[n])   * scale,
                                                      (y[jt*4+1] + biasS[n+1]) * scale);
            *(__half2*)(rowB + n) = __floats2half2_rn((y[jt*4+2] + biasS[n])   * scale,
                                                      (y[jt*4+3] + biasS[n+1]) * scale);
        }
    } else {
        __syncthreads();
        __half* tr = smq + QK_WH;
        #pragma unroll
        for (int jt = 0; jt < 32; jt++) {
            int n = jt * 8 + tig * 2;
            *(__half2*)&tr[(warp_m + g)     * P_TR + n] =
                __floats2half2_rn(y[jt*4+0] + biasS[n], y[jt*4+1] + biasS[n+1]);
            *(__half2*)&tr[(warp_m + g + 8) * P_TR + n] =
                __floats2half2_rn(y[jt*4+2] + biasS[n], y[jt*4+3] + biasS[n+1]);
        }
        __syncthreads();
        int b_ = m0 >> 12, s_base = m0 & (S_LEN - 1);
        int s = tid & 127, dh = tid >> 7;
        __half* vt = g_VTh + (size_t)b_ * DIM * S_LEN + s_base + s;
        #pragma unroll 8
        for (int i = 0; i < 128; i++) {
            int d = i * 2 + dh;
            vt[(size_t)d * S_LEN] = tr[s * P_TR + d];
        }
    }
}

// ---------------------------------------------------------------------------
// Flash attention, PV software-pipelined by one iteration.
// V triple-buffered; K single-buffered (loaded after post-S barrier).
// ---------------------------------------------------------------------------
#define A_Q   0                    // 128 x 264 halves
#define A_K   33792                // 64 x 264 (single buffer)
#define A_V   50688                // 3 x (256 x 72)
#define A_CS  105984               // 3 x 512 halves
#define ATTN_SMEM (107520 * 2)     // 215,040 B
#define VBUF_B (18432 * 2)

__global__ __launch_bounds__(256, 1) void attn_kernel(
    const float* __restrict__ beta, float* __restrict__ out)
{
    extern __shared__ __align__(16) __half smh[];
    uint32_t uS = smem_u32(smh);

    int tid = threadIdx.x;
    int lane = tid & 31, wid = tid >> 5;
    int g = lane >> 2, tig = lane & 3;
    int l7 = lane & 7, bit3 = (lane >> 3) & 1, bit4 = (lane >> 4) & 1;
    int warp_m = wid * 16;
    int b = blockIdx.y;
    int q0 = blockIdx.x * 128;

    const __half* Qg = g_Qh + ((size_t)b * S_LEN + q0) * DIM;
    const __half* Kg = g_Kh + (size_t)b * S_LEN * DIM;
    const __half* Vg = g_VTh + (size_t)b * DIM * S_LEN;

    uint32_t qa_lane = uS + (uint32_t)(A_Q + (warp_m + l7 + bit3 * 8) * 264 + bit4 * 8) * 2;
    uint32_t kb_lane = uS + (uint32_t)(A_K + (l7 + bit4 * 8) * 264 + bit3 * 8) * 2;
    uint32_t vb_lane = uS + (uint32_t)(A_V + (l7 + bit4 * 8) * 72 + bit3 * 8) * 2;

    auto load_k = [&](int it) {
        const __half* Ksrc = Kg + (size_t)(it * KVT) * DIM;
        uint32_t koff = uS + A_K * 2;
        #pragma unroll
        for (int f = tid; f < 2048; f += 256) {
            int r = f >> 5, c = f & 31;
            CP16(koff + (uint32_t)r * 528 + c * 16, Ksrc + (size_t)r * DIM + c * 8);
        }
    };
    auto load_v = [&](int it, int buf) {
        int t0 = it * KVT;
        uint32_t voff = uS + A_V * 2 + (uint32_t)buf * VBUF_B;
        const __half* Vsrc = Vg + t0;
        #pragma unroll
        for (int f = tid; f < 2048; f += 256) {
            int r = f >> 3, c = f & 7;
            CP16(voff + (uint32_t)r * 144 + c * 16, Vsrc + (size_t)r * S_LEN + c * 8);
        }
        if (tid < KVT) {
            uint32_t csoff = uS + A_CS * 2 + (uint32_t)buf * 1024;
            CP16(csoff + tid * 16, (const char*)(g_cs + t0 + tid));
        }
    };

    // prologue: Q + K(0) + V(0)/cs(0)
    #pragma unroll
    for (int f = tid; f < 4096; f += 256) {
        int r = f >> 5, c = f & 31;
        CP16(uS + A_Q * 2 + (uint32_t)r * 528 + c * 16, Qg + (size_t)r * DIM + c * 8);
    }
    load_k(0);
    load_v(0, 0);
    CP_COMMIT();

    float b0 = beta[0] * LOG2E, b1 = beta[1] * LOG2E;
    float cra[4], crb[4];
    {
        float4 ca = g_cs[q0 + warp_m + g];
        float4 cb = g_cs[q0 + warp_m + g + 8];
        cra[0] = b0 * ca.x; cra[1] = b0 * ca.y; cra[2] = b1 * ca.z; cra[3] = b1 * ca.w;
        crb[0] = b0 * cb.x; crb[1] = b0 * cb.y; crb[2] = b1 * cb.z; crb[3] = b1 * cb.w;
    }

    float o[128];
    #pragma unroll
    for (int i = 0; i < 128; i++) o[i] = 0.0f;
    float l0 = 0.0f, l1 = 0.0f;
    uint32_t ph_prev[16];

    int bufA = 2, bufB = 0, bufC = 1;   // (it-1)%3, it%3, (it+1)%3 at it=0

    #pragma unroll 1
    for (int it = 0; it < NITER; it++) {
        CP_WAIT0();
        __syncthreads();   // K(it), V(it) ready; all warps done PV(it-2) & V(it-2) reads
        if (it + 1 < NITER) { load_v(it + 1, bufC); CP_COMMIT(); }

        // ---- S = Q K^T (log2 domain) ----
        float s[32];
        #pragma unroll
        for (int i = 0; i < 32; i++) s[i] = 0.0f;
        #pragma unroll
        for (int ks = 0; ks < 16; ks++) {
            uint32_t a[4];
            ldsm4(a[0], a[1], a[2], a[3], qa_lane + ks * 32);
            #pragma unroll
            for (int j2 = 0; j2 < 4; j2++) {
                uint32_t bb[4];
                ldsm4(bb[0], bb[1], bb[2], bb[3], kb_lane + j2 * 8448 + ks * 32);
                mma16816(&s[(j2 * 2) * 4], a, &bb[0]);
                mma16816(&s[(j2 * 2 + 1) * 4], a, &bb[2]);
            }
        }
        __syncthreads();   // all warps done reading K(it)
        if (it + 1 < NITER) { load_k(it + 1); CP_COMMIT(); }

        // ---- bias + ex2 -> ph_cur ----
        const float4* csS = (const float4*)(smh + A_CS + bufB * 512);
        uint32_t ph_cur[16];
        #pragma unroll
        for (int j = 0; j < 8; j++) {
            float4 k0 = csS[j * 8 + tig * 2];
            float4 k1 = csS[j * 8 + tig * 2 + 1];
            float e0 = ex2f(s[j*4+0] + cra[0]*k0.x + cra[1]*k0.y + cra[2]*k0.z + cra[3]*k0.w);
            float e1 = ex2f(s[j*4+1] + cra[0]*k1.x + cra[1]*k1.y + cra[2]*k1.z + cra[3]*k1.w);
            float e2 = ex2f(s[j*4+2] + crb[0]*k0.x + crb[1]*k0.y + crb[2]*k0.z + crb[3]*k0.w);
            float e3 = ex2f(s[j*4+3] + crb[0]*k1.x + crb[1]*k1.y + crb[2]*k1.z + crb[3]*k1.w);
            l0 += e0 + e1; l1 += e2 + e3;
            ph_cur[j * 2]     = pk2(e0, e1);
            ph_cur[j * 2 + 1] = pk2(e2, e3);
        }

        // ---- PV(it-1): independent of softmax(it) chain -> overlaps it ----
        if (it > 0) {
            uint32_t vbuf = (uint32_t)bufA * VBUF_B;
            #pragma unroll
            for (int ks = 0; ks < 4; ks++) {
                #pragma unroll
                for (int j2 = 0; j2 < 16; j2++) {
                    uint32_t vh[4];
                    ldsm4(vh[0], vh[1], vh[2], vh[3], vb_lane + vbuf + j2 * 2304 + ks * 32);
                    mma16816(&o[(j2 * 2) * 4],     &ph_prev[ks * 4], &vh[0]);
                    mma16816(&o[(j2 * 2 + 1) * 4], &ph_prev[ks * 4], &vh[2]);
                }
            }
        }

        #pragma unroll
        for (int i = 0; i < 16; i++) ph_prev[i] = ph_cur[i];
        int t = bufA; bufA = bufB; bufB = bufC; bufC = t;
    }

    // tail: PV(NITER-1)
    {
        uint32_t vbuf = (uint32_t)((NITER - 1) % 3) * VBUF_B;
        #pragma unroll
        for (int ks = 0; ks < 4; ks++) {
            #pragma unroll
            for (int j2 = 0; j2 < 16; j2++) {
                uint32_t vh[4];
                ldsm4(vh[0], vh[1], vh[2], vh[3], vb_lane + vbuf + j2 * 2304 + ks * 32);
                mma16816(&o[(j2 * 2) * 4],     &ph_prev[ks * 4], &vh[0]);
                mma16816(&o[(j2 * 2 + 1) * 4], &ph_prev[ks * 4], &vh[2]);
            }
        }
    }

    // ---- epilogue ----
    l0 += __shfl_xor_sync(0xffffffffu, l0, 1);
    l0 += __shfl_xor_sync(0xffffffffu, l0, 2);
    l1 += __shfl_xor_sync(0xffffffffu, l1, 1);
    l1 += __shfl_xor_sync(0xffffffffu, l1, 2);
    float inv0 = 1.0f / l0, inv1 = 1.0f / l1;

    float* outA = out + ((size_t)b * S_LEN + q0 + warp_m + g) * DIM;
    float* outB = outA + 8 * DIM;
    #pragma unroll
    for (int jt = 0; jt < 32; jt++) {
        *(float2*)(outA + jt * 8 + tig * 2) = make_float2(o[jt*4+0] * inv0, o[jt*4+1] * inv0);
        *(float2*)(outB + jt * 8 + tig * 2) = make_float2(o[jt*4+2] * inv1, o[jt*4+3] * inv1);
    }
}

// ---------------------------------------------------------------------------
extern "C" void kernel_launch(void* const* d_in, const int* in_sizes, int n_in,
                              void* d_out, int out_size)
{
    const float* x    = (const float*)d_in[0];
    const float* Wq   = (const float*)d_in[1];
    const float* bq   = (const float*)d_in[2];
    const float* Wk   = (const float*)d_in[3];
    const float* bk   = (const float*)d_in[4];
    const float* Wv   = (const float*)d_in[5];
    const float* bv   = (const float*)d_in[6];
    const float* beta = (const float*)d_in[7];
    float* out = (float*)d_out;
    (void)in_sizes; (void)n_in; (void)out_size;

    cudaFuncSetAttribute(qkv_kernel,  cudaFuncAttributeMaxDynamicSharedMemorySize, QK_SMEM);
    cudaFuncSetAttribute(attn_kernel, cudaFuncAttributeMaxDynamicSharedMemorySize, ATTN_SMEM);

    cs_kernel<<<16, 256>>>();
    qkv_kernel<<<dim3(M_TOTAL / 128, 1, 3), 256, QK_SMEM>>>(x, Wq, bq, Wk, bk, Wv, bv);
    probe_kernel<<<1, 32>>>();   // spacer: lands attn on ncu's capture slot
    attn_kernel<<<dim3(S_LEN / 128, NBATCH), 256, ATTN_SMEM>>>(beta, out);
}

// round 12
// speedup vs baseline: 1.0533x; 1.0533x over previous
#include <cuda_runtime.h>
#include <cuda_fp16.h>
#include <math.h>
#include <stdint.h>

#define S_LEN 4096
#define NBATCH 4
#define DIM 256
#define M_TOTAL (NBATCH * S_LEN)
#define KVT 64
#define NITER (S_LEN / KVT)
#define LOG2E 1.4426950408889634f

// ---------------- scratch globals (fp16 precomputed operands) ----------------
__device__ __half g_Qh[M_TOTAL * DIM];              // row-major, pre-scaled log2e/16
__device__ __half g_Kh[M_TOTAL * DIM];              // row-major
__device__ __half g_VTh[NBATCH * DIM * S_LEN];      // [b][d][s]
__device__ float4 g_cs[S_LEN];                      // (cos0,sin0,cos1,sin1)

// ---------------- low-level helpers ----------------
__device__ __forceinline__ uint32_t smem_u32(const void* p) {
    uint32_t a;
    asm("{ .reg .u64 t; cvta.to.shared.u64 t, %1; cvt.u32.u64 %0, t; }" : "=r"(a) : "l"(p));
    return a;
}
__device__ __forceinline__ void ldsm4(uint32_t& r0, uint32_t& r1, uint32_t& r2, uint32_t& r3,
                                      uint32_t addr) {
    asm volatile("ldmatrix.sync.aligned.m8n8.x4.shared.b16 {%0,%1,%2,%3}, [%4];"
                 : "=r"(r0), "=r"(r1), "=r"(r2), "=r"(r3) : "r"(addr));
}
__device__ __forceinline__ void mma16816(float* d, const uint32_t* a, const uint32_t* b) {
    asm volatile("mma.sync.aligned.m16n8k16.row.col.f32.f16.f16.f32 "
                 "{%0,%1,%2,%3}, {%4,%5,%6,%7}, {%8,%9}, {%0,%1,%2,%3};"
                 : "+f"(d[0]), "+f"(d[1]), "+f"(d[2]), "+f"(d[3])
                 : "r"(a[0]), "r"(a[1]), "r"(a[2]), "r"(a[3]), "r"(b[0]), "r"(b[1]));
}
__device__ __forceinline__ uint32_t pk2(float x, float y) {
    __half2 h = __floats2half2_rn(x, y);
    return reinterpret_cast<uint32_t&>(h);
}
__device__ __forceinline__ float ex2f(float x) {
    float y; asm("ex2.approx.ftz.f32 %0, %1;" : "=f"(y) : "f"(x)); return y;
}
#define CP16(dst, src) \
    asm volatile("cp.async.cg.shared.global [%0], [%1], 16;" :: "r"(dst), "l"(src))
#define CP_COMMIT() asm volatile("cp.async.commit_group;" ::: "memory")
#define CP_WAIT0()  asm volatile("cp.async.wait_group 0;" ::: "memory")

// ---------------------------------------------------------------------------
__global__ void cs_kernel() {
    int p = blockIdx.x * blockDim.x + threadIdx.x;
    if (p < S_LEN) {
        float s0, c0, s1, c1;
        sincospif((float)(p % 24) * (1.0f / 12.0f), &s0, &c0);
        sincospif((float)(p % 720) * (1.0f / 360.0f), &s1, &c1);
        g_cs[p] = make_float4(c0, s0, c1, s1);
    }
}

// no-op spacer: keeps attn in ncu's -s 5 -c 1 capture window
__global__ void probe_kernel() {}

// ---------------------------------------------------------------------------
// QKV projection on HMMA, plain fp16 operands.
// ---------------------------------------------------------------------------
#define QK_BIAS 0
#define QK_XH 512
#define QK_WH 9728
#define QK_SMEM (43776 * 2)
#define P_TR 266

__global__ __launch_bounds__(256, 1) void qkv_kernel(
    const float* __restrict__ x,
    const float* __restrict__ Wq, const float* __restrict__ bq,
    const float* __restrict__ Wk, const float* __restrict__ bk,
    const float* __restrict__ Wv, const float* __restrict__ bv)
{
    extern __shared__ __align__(16) __half smq[];
    const float* W; const float* bias;
    int z = blockIdx.z;
    if (z == 0)      { W = Wq; bias = bq; }
    else if (z == 1) { W = Wk; bias = bk; }
    else             { W = Wv; bias = bv; }

    uint32_t uS = smem_u32(smq);
    int tid = threadIdx.x;
    int lane = tid & 31, wid = tid >> 5;
    int g = lane >> 2, tig = lane & 3;
    int l7 = lane & 7, bit3 = (lane >> 3) & 1, bit4 = (lane >> 4) & 1;
    int warp_m = wid * 16;
    int m0 = blockIdx.x * 128;

    float* biasS = (float*)(smq + QK_BIAS);
    if (tid < 256) biasS[tid] = bias[tid];

    uint32_t xa_h = uS + (uint32_t)(QK_XH + (warp_m + l7 + bit3 * 8) * 72 + bit4 * 8) * 2;
    uint32_t wb_h = uS + (uint32_t)(QK_WH + (l7 + bit4 * 8) * 72 + bit3 * 8) * 2;

    float y[128];
    #pragma unroll
    for (int i = 0; i < 128; i++) y[i] = 0.0f;

    #pragma unroll 1
    for (int k0 = 0; k0 < DIM; k0 += 64) {
        __syncthreads();
        for (int f = tid; f < 2048; f += 256) {
            int r = f >> 4, c = (f & 15) * 4;
            float4 v = *(const float4*)(x + (size_t)(m0 + r) * DIM + k0 + c);
            *(__half2*)&smq[QK_XH + r * 72 + c]     = __floats2half2_rn(v.x, v.y);
            *(__half2*)&smq[QK_XH + r * 72 + c + 2] = __floats2half2_rn(v.z, v.w);
        }
        for (int f = tid; f < 4096; f += 256) {
            int r = f >> 4, c = (f & 15) * 4;
            float4 v = *(const float4*)(W + (size_t)r * DIM + k0 + c);
            *(__half2*)&smq[QK_WH + r * 72 + c]     = __floats2half2_rn(v.x, v.y);
            *(__half2*)&smq[QK_WH + r * 72 + c + 2] = __floats2half2_rn(v.z, v.w);
        }
        __syncthreads();

        #pragma unroll
        for (int ks = 0; ks < 4; ks++) {
            uint32_t ah[4];
            ldsm4(ah[0], ah[1], ah[2], ah[3], xa_h + ks * 32);
            #pragma unroll
            for (int j2 = 0; j2 < 16; j2++) {
                uint32_t bh[4];
                ldsm4(bh[0], bh[1], bh[2], bh[3], wb_h + j2 * 2304 + ks * 32);
                mma16816(&y[(j2 * 2) * 4],     ah, &bh[0]);
                mma16816(&y[(j2 * 2 + 1) * 4], ah, &bh[2]);
            }
        }
    }

    if (z < 2) {
        float scale = (z == 0) ? (LOG2E / 16.0f) : 1.0f;
        __half* dst = ((z == 0) ? g_Qh : g_Kh);
        __half* rowA = dst + (size_t)(m0 + warp_m + g) * DIM;
        __half* rowB = rowA + 8 * DIM;
        #pragma unroll
        for (int jt = 0; jt < 32; jt++) {
            int n = jt * 8 + tig * 2;
            *(__half2*)(rowA + n) = __floats2half2_rn((y[jt*4+0] + biasS[n])   * scale,
                                                      (y[jt*4+1] + biasS[n+1]) * scale);
            *(__half2*)(rowB + n) = __floats2half2_rn((y[jt*4+2] + biasS[n])   * scale,
                                                      (y[jt*4+3] + biasS[n+1]) * scale);
        }
    } else {
        __syncthreads();
        __half* tr = smq + QK_WH;
        #pragma unroll
        for (int jt = 0; jt < 32; jt++) {
            int n = jt * 8 + tig * 2;
            *(__half2*)&tr[(warp_m + g)     * P_TR + n] =
                __floats2half2_rn(y[jt*4+0] + biasS[n], y[jt*4+1] + biasS[n+1]);
            *(__half2*)&tr[(warp_m + g + 8) * P_TR + n] =
                __floats2half2_rn(y[jt*4+2] + biasS[n], y[jt*4+3] + biasS[n+1]);
        }
        __syncthreads();
        int b_ = m0 >> 12, s_base = m0 & (S_LEN - 1);
        int s = tid & 127, dh = tid >> 7;
        __half* vt = g_VTh + (size_t)b_ * DIM * S_LEN + s_base + s;
        #pragma unroll 8
        for (int i = 0; i < 128; i++) {
            int d = i * 2 + dh;
            vt[(size_t)d * S_LEN] = tr[s * P_TR + d];
        }
    }
}

// ---------------------------------------------------------------------------
// Flash attention on HMMA, round-10 structure (double-buffered, 1 barrier/iter),
// with softmax and PV interleaved in 4 ks-chunks (zero extra regs/barriers):
// ex2-chunk(ks+1) latency hides under PV-MMA issue of chunk ks.
// ---------------------------------------------------------------------------
#define A_Q   0                  // 128 x 264
#define A_K0  33792              // 64 x 264  (x2 buffers)
#define A_V0  67584              // 256 x 72  (x2 buffers)
#define A_CS0 104448             // 64 float4 = 512 halves  (x2 buffers)
#define ATTN_SMEM (105472 * 2)   // 210,944 B
#define KBUF_B (16896 * 2)
#define VBUF_B (18432 * 2)

__global__ __launch_bounds__(256, 1) void attn_kernel(
    const float* __restrict__ beta, float* __restrict__ out)
{
    extern __shared__ __align__(16) __half smh[];
    uint32_t uS = smem_u32(smh);

    int tid = threadIdx.x;
    int lane = tid & 31, wid = tid >> 5;
    int g = lane >> 2, tig = lane & 3;
    int l7 = lane & 7, bit3 = (lane >> 3) & 1, bit4 = (lane >> 4) & 1;
    int warp_m = wid * 16;
    int b = blockIdx.y;
    int q0 = blockIdx.x * 128;

    const __half* Qg = g_Qh + ((size_t)b * S_LEN + q0) * DIM;
    const __half* Kg = g_Kh + (size_t)b * S_LEN * DIM;
    const __half* Vg = g_VTh + (size_t)b * DIM * S_LEN;

    uint32_t qa_lane = uS + (uint32_t)(A_Q + (warp_m + l7 + bit3 * 8) * 264 + bit4 * 8) * 2;
    uint32_t kb_lane = uS + (uint32_t)(A_K0 + (l7 + bit4 * 8) * 264 + bit3 * 8) * 2;
    uint32_t vb_lane = uS + (uint32_t)(A_V0 + (l7 + bit4 * 8) * 72 + bit3 * 8) * 2;

    // ---- async tile loaders ----
    auto load_kv = [&](int it) {
        int t0 = it * KVT;
        uint32_t koff = uS + A_K0 * 2 + (it & 1) * KBUF_B;
        uint32_t voff = uS + A_V0 * 2 + (it & 1) * VBUF_B;
        const __half* Ksrc = Kg + (size_t)t0 * DIM;
        const __half* Vsrc = Vg + t0;
        #pragma unroll
        for (int f = tid; f < 2048; f += 256) {       // K: 64 rows x 32 chunks
            int r = f >> 5, c = f & 31;
            CP16(koff + (uint32_t)r * 528 + c * 16, Ksrc + (size_t)r * DIM + c * 8);
        }
        #pragma unroll
        for (int f = tid; f < 2048; f += 256) {       // V^T: 256 rows x 8 chunks
            int r = f >> 3, c = f & 7;
            CP16(voff + (uint32_t)r * 144 + c * 16, Vsrc + (size_t)r * S_LEN + c * 8);
        }
        if (tid < KVT) {
            uint32_t csoff = uS + A_CS0 * 2 + (it & 1) * 1024;
            CP16(csoff + tid * 16, (const char*)(g_cs + t0 + tid));
        }
    };

    // prologue: Q + tiles for iter 0
    #pragma unroll
    for (int f = tid; f < 4096; f += 256) {           // Q: 128 rows x 32 chunks
        int r = f >> 5, c = f & 31;
        CP16(uS + A_Q * 2 + (uint32_t)r * 528 + c * 16, Qg + (size_t)r * DIM + c * 8);
    }
    load_kv(0);
    CP_COMMIT();

    float b0 = beta[0] * LOG2E, b1 = beta[1] * LOG2E;
    float cra[4], crb[4];
    {
        float4 ca = g_cs[q0 + warp_m + g];
        float4 cb = g_cs[q0 + warp_m + g + 8];
        cra[0] = b0 * ca.x; cra[1] = b0 * ca.y; cra[2] = b1 * ca.z; cra[3] = b1 * ca.w;
        crb[0] = b0 * cb.x; crb[1] = b0 * cb.y; crb[2] = b1 * cb.z; crb[3] = b1 * cb.w;
    }

    float o[128];
    #pragma unroll
    for (int i = 0; i < 128; i++) o[i] = 0.0f;
    float l0 = 0.0f, l1 = 0.0f;

    #pragma unroll 1
    for (int it = 0; it < NITER; it++) {
        CP_WAIT0();
        __syncthreads();   // buffer it ready for all; all warps done with buffer it-1
        if (it + 1 < NITER) { load_kv(it + 1); CP_COMMIT(); }

        uint32_t kbuf = (it & 1) * KBUF_B, vbuf = (it & 1) * VBUF_B;
        const float4* csS = (const float4*)(smh + A_CS0 + (it & 1) * 512);

        // ---- S = Q K^T (log2 domain: Q pre-scaled) ----
        float s[32];
        #pragma unroll
        for (int i = 0; i < 32; i++) s[i] = 0.0f;
        #pragma unroll
        for (int ks = 0; ks < 16; ks++) {
            uint32_t a[4];
            ldsm4(a[0], a[1], a[2], a[3], qa_lane + ks * 32);
            #pragma unroll
            for (int j2 = 0; j2 < 4; j2++) {
                uint32_t bb[4];
                ldsm4(bb[0], bb[1], bb[2], bb[3], kb_lane + kbuf + j2 * 8448 + ks * 32);
                mma16816(&s[(j2 * 2) * 4], a, &bb[0]);
                mma16816(&s[(j2 * 2 + 1) * 4], a, &bb[2]);
            }
        }

        // ---- softmax chunk(ks) then PV chunk(ks): ex2 latency of chunk ks+1
        //      overlaps PV MMA issue of chunk ks ----
        #pragma unroll
        for (int ks = 0; ks < 4; ks++) {
            uint32_t ph[4];
            #pragma unroll
            for (int jj = 0; jj < 2; jj++) {
                int j = ks * 2 + jj;
                float4 k0 = csS[j * 8 + tig * 2];
                float4 k1 = csS[j * 8 + tig * 2 + 1];
                float e0 = ex2f(s[j*4+0] + cra[0]*k0.x + cra[1]*k0.y + cra[2]*k0.z + cra[3]*k0.w);
                float e1 = ex2f(s[j*4+1] + cra[0]*k1.x + cra[1]*k1.y + cra[2]*k1.z + cra[3]*k1.w);
                float e2 = ex2f(s[j*4+2] + crb[0]*k0.x + crb[1]*k0.y + crb[2]*k0.z + crb[3]*k0.w);
                float e3 = ex2f(s[j*4+3] + crb[0]*k1.x + crb[1]*k1.y + crb[2]*k1.z + crb[3]*k1.w);
                l0 += e0 + e1; l1 += e2 + e3;
                ph[jj * 2]     = pk2(e0, e1);
                ph[jj * 2 + 1] = pk2(e2, e3);
            }
            #pragma unroll
            for (int j2 = 0; j2 < 16; j2++) {
                uint32_t vh[4];
                ldsm4(vh[0], vh[1], vh[2], vh[3], vb_lane + vbuf + j2 * 2304 + ks * 32);
                mma16816(&o[(j2 * 2) * 4],     ph, &vh[0]);
                mma16816(&o[(j2 * 2 + 1) * 4], ph, &vh[2]);
            }
        }
        // (no trailing sync: next iter's top barrier orders buffer reuse)
    }

    // ---- epilogue ----
    l0 += __shfl_xor_sync(0xffffffffu, l0, 1);
    l0 += __shfl_xor_sync(0xffffffffu, l0, 2);
    l1 += __shfl_xor_sync(0xffffffffu, l1, 1);
    l1 += __shfl_xor_sync(0xffffffffu, l1, 2);
    float inv0 = 1.0f / l0, inv1 = 1.0f / l1;

    float* outA = out + ((size_t)b * S_LEN + q0 + warp_m + g) * DIM;
    float* outB = outA + 8 * DIM;
    #pragma unroll
    for (int jt = 0; jt < 32; jt++) {
        *(float2*)(outA + jt * 8 + tig * 2) = make_float2(o[jt*4+0] * inv0, o[jt*4+1] * inv0);
        *(float2*)(outB + jt * 8 + tig * 2) = make_float2(o[jt*4+2] * inv1, o[jt*4+3] * inv1);
    }
}

// ---------------------------------------------------------------------------
extern "C" void kernel_launch(void* const* d_in, const int* in_sizes, int n_in,
                              void* d_out, int out_size)
{
    const float* x    = (const float*)d_in[0];
    const float* Wq   = (const float*)d_in[1];
    const float* bq   = (const float*)d_in[2];
    const float* Wk   = (const float*)d_in[3];
    const float* bk   = (const float*)d_in[4];
    const float* Wv   = (const float*)d_in[5];
    const float* bv   = (const float*)d_in[6];
    const float* beta = (const float*)d_in[7];
    float* out = (float*)d_out;
    (void)in_sizes; (void)n_in; (void)out_size;

    cudaFuncSetAttribute(qkv_kernel,  cudaFuncAttributeMaxDynamicSharedMemorySize, QK_SMEM);
    cudaFuncSetAttribute(attn_kernel, cudaFuncAttributeMaxDynamicSharedMemorySize, ATTN_SMEM);

    cs_kernel<<<16, 256>>>();
    qkv_kernel<<<dim3(M_TOTAL / 128, 1, 3), 256, QK_SMEM>>>(x, Wq, bq, Wk, bk, Wv, bv);
    probe_kernel<<<1, 32>>>();   // spacer: lands attn on ncu's capture slot
    attn_kernel<<<dim3(S_LEN / 128, NBATCH), 256, ATTN_SMEM>>>(beta, out);
}

// round 13
// speedup vs baseline: 1.0748x; 1.0204x over previous
#include <cuda_runtime.h>
#include <cuda_fp16.h>
#include <math.h>
#include <stdint.h>

#define S_LEN 4096
#define NBATCH 4
#define DIM 256
#define M_TOTAL (NBATCH * S_LEN)
#define KVT 64
#define NITER (S_LEN / KVT)
#define LOG2E 1.4426950408889634f

// ---------------- scratch globals (fp16 precomputed operands) ----------------
__device__ __half g_xh[M_TOTAL * DIM];              // fp16(x), row-major
__device__ __half g_Wh[3 * DIM * DIM];              // fp16(Wq|Wk|Wv), row-major
__device__ __half g_Qh[M_TOTAL * DIM];              // row-major, pre-scaled log2e/16
__device__ __half g_Kh[M_TOTAL * DIM];              // row-major
__device__ __half g_VTh[NBATCH * DIM * S_LEN];      // [b][d][s]
__device__ float4 g_cs[S_LEN];                      // (cos0,sin0,cos1,sin1)

// ---------------- low-level helpers ----------------
__device__ __forceinline__ uint32_t smem_u32(const void* p) {
    uint32_t a;
    asm("{ .reg .u64 t; cvta.to.shared.u64 t, %1; cvt.u32.u64 %0, t; }" : "=r"(a) : "l"(p));
    return a;
}
__device__ __forceinline__ void ldsm4(uint32_t& r0, uint32_t& r1, uint32_t& r2, uint32_t& r3,
                                      uint32_t addr) {
    asm volatile("ldmatrix.sync.aligned.m8n8.x4.shared.b16 {%0,%1,%2,%3}, [%4];"
                 : "=r"(r0), "=r"(r1), "=r"(r2), "=r"(r3) : "r"(addr));
}
__device__ __forceinline__ void mma16816(float* d, const uint32_t* a, const uint32_t* b) {
    asm volatile("mma.sync.aligned.m16n8k16.row.col.f32.f16.f16.f32 "
                 "{%0,%1,%2,%3}, {%4,%5,%6,%7}, {%8,%9}, {%0,%1,%2,%3};"
                 : "+f"(d[0]), "+f"(d[1]), "+f"(d[2]), "+f"(d[3])
                 : "r"(a[0]), "r"(a[1]), "r"(a[2]), "r"(a[3]), "r"(b[0]), "r"(b[1]));
}
__device__ __forceinline__ uint32_t pk2(float x, float y) {
    __half2 h = __floats2half2_rn(x, y);
    return reinterpret_cast<uint32_t&>(h);
}
__device__ __forceinline__ float ex2f(float x) {
    float y; asm("ex2.approx.ftz.f32 %0, %1;" : "=f"(y) : "f"(x)); return y;
}
#define CP16(dst, src) \
    asm volatile("cp.async.cg.shared.global [%0], [%1], 16;" :: "r"(dst), "l"(src))
#define CP_COMMIT() asm volatile("cp.async.commit_group;" ::: "memory")
#define CP_WAIT0()  asm volatile("cp.async.wait_group 0;" ::: "memory")

// ---------------------------------------------------------------------------
__global__ void cs_kernel() {
    int p = blockIdx.x * blockDim.x + threadIdx.x;
    if (p < S_LEN) {
        float s0, c0, s1, c1;
        sincospif((float)(p % 24) * (1.0f / 12.0f), &s0, &c0);
        sincospif((float)(p % 720) * (1.0f / 360.0f), &s1, &c1);
        g_cs[p] = make_float4(c0, s0, c1, s1);
    }
}

// fp32 -> fp16 pre-conversion of x and W (bit-identical to qkv's old in-kernel cvt)
#define XCHUNKS (M_TOTAL * DIM / 8)        // 524288
#define WCHUNKS (3 * DIM * DIM / 8)        // 24576
__global__ __launch_bounds__(256) void prep_kernel(
    const float* __restrict__ x,
    const float* __restrict__ Wq, const float* __restrict__ Wk, const float* __restrict__ Wv)
{
    int idx = blockIdx.x * blockDim.x + threadIdx.x;
    const float* src; __half* dst; int e;
    if (idx < XCHUNKS) {
        src = x; dst = g_xh; e = idx * 8;
    } else {
        int widx = idx - XCHUNKS;
        if (widx >= WCHUNKS) return;
        int we = widx * 8;
        int z = we >> 16;                   // 65536 = DIM*DIM
        src = (z == 0) ? Wq : (z == 1) ? Wk : Wv;
        dst = g_Wh + (z << 16);
        e = we & 65535;
        src -= 0; // rows within W
        // adjust: src indexes within the selected W
        float4 v0 = *(const float4*)(src + e);
        float4 v1 = *(const float4*)(src + e + 4);
        __half2* d2 = (__half2*)(dst + e);
        d2[0] = __floats2half2_rn(v0.x, v0.y);
        d2[1] = __floats2half2_rn(v0.z, v0.w);
        d2[2] = __floats2half2_rn(v1.x, v1.y);
        d2[3] = __floats2half2_rn(v1.z, v1.w);
        return;
    }
    float4 v0 = *(const float4*)(src + e);
    float4 v1 = *(const float4*)(src + e + 4);
    __half2* d2 = (__half2*)(dst + e);
    d2[0] = __floats2half2_rn(v0.x, v0.y);
    d2[1] = __floats2half2_rn(v0.z, v0.w);
    d2[2] = __floats2half2_rn(v1.x, v1.y);
    d2[3] = __floats2half2_rn(v1.z, v1.w);
}

// no-op spacer: keeps attn in ncu's -s 5 -c 1 capture window
__global__ void probe_kernel() {}

// ---------------------------------------------------------------------------
// QKV projection on HMMA, fp16 operands cp.async'd from global (double-buffered).
// z=0: Q (scaled log2e/16) -> g_Qh ; z=1: K -> g_Kh ; z=2: V -> g_VTh (transposed).
// ---------------------------------------------------------------------------
#define QK_BIAS 0                 // 256 floats = 512 halves
#define QK_X0 512                 // 128*72 halves, x2 buffers
#define QK_W0 18944               // 256*72 halves, x2 buffers
#define QK_SMEM (55808 * 2)       // 111,616 B
#define XBUF_H 9216
#define WBUF_H 18432
#define P_TR 266                  // transpose staging pitch (over W buffers)

__global__ __launch_bounds__(256, 1) void qkv_kernel(
    const float* __restrict__ bq, const float* __restrict__ bk, const float* __restrict__ bv)
{
    extern __shared__ __align__(16) __half smq[];
    int z = blockIdx.z;
    const float* bias = (z == 0) ? bq : (z == 1) ? bk : bv;
    const __half* Wsrc = g_Wh + (z << 16);

    uint32_t uS = smem_u32(smq);
    int tid = threadIdx.x;
    int lane = tid & 31, wid = tid >> 5;
    int g = lane >> 2, tig = lane & 3;
    int l7 = lane & 7, bit3 = (lane >> 3) & 1, bit4 = (lane >> 4) & 1;
    int warp_m = wid * 16;
    int m0 = blockIdx.x * 128;
    const __half* Xsrc = g_xh + (size_t)m0 * DIM;

    float* biasS = (float*)(smq + QK_BIAS);
    if (tid < 256) biasS[tid] = bias[tid];

    uint32_t xa_h = uS + (uint32_t)(QK_X0 + (warp_m + l7 + bit3 * 8) * 72 + bit4 * 8) * 2;
    uint32_t wb_h = uS + (uint32_t)(QK_W0 + (l7 + bit4 * 8) * 72 + bit3 * 8) * 2;

    // async chunk loader: x 128x64, W 256x64 (fp16, padded pitch 72)
    auto load_chunk = [&](int c) {
        int k0 = c * 64;
        uint32_t xoff = uS + (QK_X0 + (c & 1) * XBUF_H) * 2;
        uint32_t woff = uS + (QK_W0 + (c & 1) * WBUF_H) * 2;
        #pragma unroll
        for (int f = tid; f < 1024; f += 256) {       // x: 128 rows x 8 chunks
            int r = f >> 3, cc = f & 7;
            CP16(xoff + (uint32_t)r * 144 + cc * 16, Xsrc + (size_t)r * DIM + k0 + cc * 8);
        }
        #pragma unroll
        for (int f = tid; f < 2048; f += 256) {       // W: 256 rows x 8 chunks
            int r = f >> 3, cc = f & 7;
            CP16(woff + (uint32_t)r * 144 + cc * 16, Wsrc + (size_t)r * DIM + k0 + cc * 8);
        }
    };

    load_chunk(0);
    CP_COMMIT();

    float y[128];
    #pragma unroll
    for (int i = 0; i < 128; i++) y[i] = 0.0f;

    #pragma unroll 1
    for (int c = 0; c < 4; c++) {
        CP_WAIT0();
        __syncthreads();
        if (c + 1 < 4) { load_chunk(c + 1); CP_COMMIT(); }

        uint32_t xbuf = (uint32_t)(c & 1) * (XBUF_H * 2);
        uint32_t wbuf = (uint32_t)(c & 1) * (WBUF_H * 2);
        #pragma unroll
        for (int ks = 0; ks < 4; ks++) {
            uint32_t ah[4];
            ldsm4(ah[0], ah[1], ah[2], ah[3], xa_h + xbuf + ks * 32);
            #pragma unroll
            for (int j2 = 0; j2 < 16; j2++) {
                uint32_t bh[4];
                ldsm4(bh[0], bh[1], bh[2], bh[3], wb_h + wbuf + j2 * 2304 + ks * 32);
                mma16816(&y[(j2 * 2) * 4],     ah, &bh[0]);
                mma16816(&y[(j2 * 2 + 1) * 4], ah, &bh[2]);
            }
        }
    }

    if (z < 2) {
        float scale = (z == 0) ? (LOG2E / 16.0f) : 1.0f;
        __half* dst = ((z == 0) ? g_Qh : g_Kh);
        __half* rowA = dst + (size_t)(m0 + warp_m + g) * DIM;
        __half* rowB = rowA + 8 * DIM;
        #pragma unroll
        for (int jt = 0; jt < 32; jt++) {
            int n = jt * 8 + tig * 2;
            *(__half2*)(rowA + n) = __floats2half2_rn((y[jt*4+0] + biasS[n])   * scale,
                                                      (y[jt*4+1] + biasS[n+1]) * scale);
            *(__half2*)(rowB + n) = __floats2half2_rn((y[jt*4+2] + biasS[n])   * scale,
                                                      (y[jt*4+3] + biasS[n+1]) * scale);
        }
    } else {
        __syncthreads();
        __half* tr = smq + QK_W0;    // staging over W buffers (36864 halves >= 34048)
        #pragma unroll
        for (int jt = 0; jt < 32; jt++) {
            int n = jt * 8 + tig * 2;
            *(__half2*)&tr[(warp_m + g)     * P_TR + n] =
                __floats2half2_rn(y[jt*4+0] + biasS[n], y[jt*4+1] + biasS[n+1]);
            *(__half2*)&tr[(warp_m + g + 8) * P_TR + n] =
                __floats2half2_rn(y[jt*4+2] + biasS[n], y[jt*4+3] + biasS[n+1]);
        }
        __syncthreads();
        int b_ = m0 >> 12, s_base = m0 & (S_LEN - 1);
        int s = tid & 127, dh = tid >> 7;
        __half* vt = g_VTh + (size_t)b_ * DIM * S_LEN + s_base + s;
        #pragma unroll 8
        for (int i = 0; i < 128; i++) {
            int d = i * 2 + dh;
            vt[(size_t)d * S_LEN] = tr[s * P_TR + d];
        }
    }
}

// ---------------------------------------------------------------------------
// Flash attention on HMMA (round-10/12 proven structure, untouched).
// ---------------------------------------------------------------------------
#define A_Q   0                  // 128 x 264
#define A_K0  33792              // 64 x 264  (x2 buffers)
#define A_V0  67584              // 256 x 72  (x2 buffers)
#define A_CS0 104448             // 64 float4 = 512 halves  (x2 buffers)
#define ATTN_SMEM (105472 * 2)   // 210,944 B
#define KBUF_B (16896 * 2)
#define VBUF_B (18432 * 2)

__global__ __launch_bounds__(256, 1) void attn_kernel(
    const float* __restrict__ beta, float* __restrict__ out)
{
    extern __shared__ __align__(16) __half smh[];
    uint32_t uS = smem_u32(smh);

    int tid = threadIdx.x;
    int lane = tid & 31, wid = tid >> 5;
    int g = lane >> 2, tig = lane & 3;
    int l7 = lane & 7, bit3 = (lane >> 3) & 1, bit4 = (lane >> 4) & 1;
    int warp_m = wid * 16;
    int b = blockIdx.y;
    int q0 = blockIdx.x * 128;

    const __half* Qg = g_Qh + ((size_t)b * S_LEN + q0) * DIM;
    const __half* Kg = g_Kh + (size_t)b * S_LEN * DIM;
    const __half* Vg = g_VTh + (size_t)b * DIM * S_LEN;

    uint32_t qa_lane = uS + (uint32_t)(A_Q + (warp_m + l7 + bit3 * 8) * 264 + bit4 * 8) * 2;
    uint32_t kb_lane = uS + (uint32_t)(A_K0 + (l7 + bit4 * 8) * 264 + bit3 * 8) * 2;
    uint32_t vb_lane = uS + (uint32_t)(A_V0 + (l7 + bit4 * 8) * 72 + bit3 * 8) * 2;

    auto load_kv = [&](int it) {
        int t0 = it * KVT;
        uint32_t koff = uS + A_K0 * 2 + (it & 1) * KBUF_B;
        uint32_t voff = uS + A_V0 * 2 + (it & 1) * VBUF_B;
        const __half* Ksrc = Kg + (size_t)t0 * DIM;
        const __half* Vsrc = Vg + t0;
        #pragma unroll
        for (int f = tid; f < 2048; f += 256) {
            int r = f >> 5, c = f & 31;
            CP16(koff + (uint32_t)r * 528 + c * 16, Ksrc + (size_t)r * DIM + c * 8);
        }
        #pragma unroll
        for (int f = tid; f < 2048; f += 256) {
            int r = f >> 3, c = f & 7;
            CP16(voff + (uint32_t)r * 144 + c * 16, Vsrc + (size_t)r * S_LEN + c * 8);
        }
        if (tid < KVT) {
            uint32_t csoff = uS + A_CS0 * 2 + (it & 1) * 1024;
            CP16(csoff + tid * 16, (const char*)(g_cs + t0 + tid));
        }
    };

    #pragma unroll
    for (int f = tid; f < 4096; f += 256) {
        int r = f >> 5, c = f & 31;
        CP16(uS + A_Q * 2 + (uint32_t)r * 528 + c * 16, Qg + (size_t)r * DIM + c * 8);
    }
    load_kv(0);
    CP_COMMIT();

    float b0 = beta[0] * LOG2E, b1 = beta[1] * LOG2E;
    float cra[4], crb[4];
    {
        float4 ca = g_cs[q0 + warp_m + g];
        float4 cb = g_cs[q0 + warp_m + g + 8];
        cra[0] = b0 * ca.x; cra[1] = b0 * ca.y; cra[2] = b1 * ca.z; cra[3] = b1 * ca.w;
        crb[0] = b0 * cb.x; crb[1] = b0 * cb.y; crb[2] = b1 * cb.z; crb[3] = b1 * cb.w;
    }

    float o[128];
    #pragma unroll
    for (int i = 0; i < 128; i++) o[i] = 0.0f;
    float l0 = 0.0f, l1 = 0.0f;

    #pragma unroll 1
    for (int it = 0; it < NITER; it++) {
        CP_WAIT0();
        __syncthreads();
        if (it + 1 < NITER) { load_kv(it + 1); CP_COMMIT(); }

        uint32_t kbuf = (it & 1) * KBUF_B, vbuf = (it & 1) * VBUF_B;
        const float4* csS = (const float4*)(smh + A_CS0 + (it & 1) * 512);

        float s[32];
        #pragma unroll
        for (int i = 0; i < 32; i++) s[i] = 0.0f;
        #pragma unroll
        for (int ks = 0; ks < 16; ks++) {
            uint32_t a[4];
            ldsm4(a[0], a[1], a[2], a[3], qa_lane + ks * 32);
            #pragma unroll
            for (int j2 = 0; j2 < 4; j2++) {
                uint32_t bb[4];
                ldsm4(bb[0], bb[1], bb[2], bb[3], kb_lane + kbuf + j2 * 8448 + ks * 32);
                mma16816(&s[(j2 * 2) * 4], a, &bb[0]);
                mma16816(&s[(j2 * 2 + 1) * 4], a, &bb[2]);
            }
        }

        #pragma unroll
        for (int ks = 0; ks < 4; ks++) {
            uint32_t ph[4];
            #pragma unroll
            for (int jj = 0; jj < 2; jj++) {
                int j = ks * 2 + jj;
                float4 k0 = csS[j * 8 + tig * 2];
                float4 k1 = csS[j * 8 + tig * 2 + 1];
                float e0 = ex2f(s[j*4+0] + cra[0]*k0.x + cra[1]*k0.y + cra[2]*k0.z + cra[3]*k0.w);
                float e1 = ex2f(s[j*4+1] + cra[0]*k1.x + cra[1]*k1.y + cra[2]*k1.z + cra[3]*k1.w);
                float e2 = ex2f(s[j*4+2] + crb[0]*k0.x + crb[1]*k0.y + crb[2]*k0.z + crb[3]*k0.w);
                float e3 = ex2f(s[j*4+3] + crb[0]*k1.x + crb[1]*k1.y + crb[2]*k1.z + crb[3]*k1.w);
                l0 += e0 + e1; l1 += e2 + e3;
                ph[jj * 2]     = pk2(e0, e1);
                ph[jj * 2 + 1] = pk2(e2, e3);
            }
            #pragma unroll
            for (int j2 = 0; j2 < 16; j2++) {
                uint32_t vh[4];
                ldsm4(vh[0], vh[1], vh[2], vh[3], vb_lane + vbuf + j2 * 2304 + ks * 32);
                mma16816(&o[(j2 * 2) * 4],     ph, &vh[0]);
                mma16816(&o[(j2 * 2 + 1) * 4], ph, &vh[2]);
            }
        }
    }

    l0 += __shfl_xor_sync(0xffffffffu, l0, 1);
    l0 += __shfl_xor_sync(0xffffffffu, l0, 2);
    l1 += __shfl_xor_sync(0xffffffffu, l1, 1);
    l1 += __shfl_xor_sync(0xffffffffu, l1, 2);
    float inv0 = 1.0f / l0, inv1 = 1.0f / l1;

    float* outA = out + ((size_t)b * S_LEN + q0 + warp_m + g) * DIM;
    float* outB = outA + 8 * DIM;
    #pragma unroll
    for (int jt = 0; jt < 32; jt++) {
        *(float2*)(outA + jt * 8 + tig * 2) = make_float2(o[jt*4+0] * inv0, o[jt*4+1] * inv0);
        *(float2*)(outB + jt * 8 + tig * 2) = make_float2(o[jt*4+2] * inv1, o[jt*4+3] * inv1);
    }
}

// ---------------------------------------------------------------------------
extern "C" void kernel_launch(void* const* d_in, const int* in_sizes, int n_in,
                              void* d_out, int out_size)
{
    const float* x    = (const float*)d_in[0];
    const float* Wq   = (const float*)d_in[1];
    const float* bq   = (const float*)d_in[2];
    const float* Wk   = (const float*)d_in[3];
    const float* bk   = (const float*)d_in[4];
    const float* Wv   = (const float*)d_in[5];
    const float* bv   = (const float*)d_in[6];
    const float* beta = (const float*)d_in[7];
    float* out = (float*)d_out;
    (void)in_sizes; (void)n_in; (void)out_size;

    cudaFuncSetAttribute(qkv_kernel,  cudaFuncAttributeMaxDynamicSharedMemorySize, QK_SMEM);
    cudaFuncSetAttribute(attn_kernel, cudaFuncAttributeMaxDynamicSharedMemorySize, ATTN_SMEM);

    cs_kernel<<<16, 256>>>();
    prep_kernel<<<(XCHUNKS + WCHUNKS + 255) / 256, 256>>>(x, Wq, Wk, Wv);
    qkv_kernel<<<dim3(M_TOTAL / 128, 1, 3), 256, QK_SMEM>>>(bq, bk, bv);
    probe_kernel<<<1, 32>>>();   // spacer: lands attn on ncu's capture slot
    attn_kernel<<<dim3(S_LEN / 128, NBATCH), 256, ATTN_SMEM>>>(beta, out);
}

// round 14
// speedup vs baseline: 1.0906x; 1.0147x over previous
#include <cuda_runtime.h>
#include <cuda_fp16.h>
#include <math.h>
#include <stdint.h>

#define S_LEN 4096
#define NBATCH 4
#define DIM 256
#define M_TOTAL (NBATCH * S_LEN)
#define KVT 64
#define NITER (S_LEN / KVT)
#define LOG2E 1.4426950408889634f

// ---------------- scratch globals (fp16 precomputed operands) ----------------
__device__ __half g_xh[M_TOTAL * DIM];              // fp16(x), row-major
__device__ __half g_Wh[3 * DIM * DIM];              // fp16(Wq|Wk|Wv), row-major
__device__ __half g_Qh[M_TOTAL * DIM];              // row-major, pre-scaled log2e/16
__device__ __half g_Kh[M_TOTAL * DIM];              // row-major
__device__ __half g_VTh[NBATCH * DIM * S_LEN];      // [b][d][s]
__device__ float4 g_cs[S_LEN];                      // (cos0,sin0,cos1,sin1)

// ---------------- low-level helpers ----------------
__device__ __forceinline__ uint32_t smem_u32(const void* p) {
    uint32_t a;
    asm("{ .reg .u64 t; cvta.to.shared.u64 t, %1; cvt.u32.u64 %0, t; }" : "=r"(a) : "l"(p));
    return a;
}
__device__ __forceinline__ void ldsm4(uint32_t& r0, uint32_t& r1, uint32_t& r2, uint32_t& r3,
                                      uint32_t addr) {
    asm volatile("ldmatrix.sync.aligned.m8n8.x4.shared.b16 {%0,%1,%2,%3}, [%4];"
                 : "=r"(r0), "=r"(r1), "=r"(r2), "=r"(r3) : "r"(addr));
}
__device__ __forceinline__ void mma16816(float* d, const uint32_t* a, const uint32_t* b) {
    asm volatile("mma.sync.aligned.m16n8k16.row.col.f32.f16.f16.f32 "
                 "{%0,%1,%2,%3}, {%4,%5,%6,%7}, {%8,%9}, {%0,%1,%2,%3};"
                 : "+f"(d[0]), "+f"(d[1]), "+f"(d[2]), "+f"(d[3])
                 : "r"(a[0]), "r"(a[1]), "r"(a[2]), "r"(a[3]), "r"(b[0]), "r"(b[1]));
}
__device__ __forceinline__ uint32_t pk2(float x, float y) {
    __half2 h = __floats2half2_rn(x, y);
    return reinterpret_cast<uint32_t&>(h);
}
__device__ __forceinline__ float ex2f(float x) {
    float y; asm("ex2.approx.ftz.f32 %0, %1;" : "=f"(y) : "f"(x)); return y;
}
#define CP16(dst, src) \
    asm volatile("cp.async.cg.shared.global [%0], [%1], 16;" :: "r"(dst), "l"(src))
#define CP_COMMIT() asm volatile("cp.async.commit_group;" ::: "memory")
#define CP_WAIT0()  asm volatile("cp.async.wait_group 0;" ::: "memory")

// ---------------------------------------------------------------------------
// prep: cos/sin table + fp32->fp16 conversion of x and all W (one launch)
// ---------------------------------------------------------------------------
#define XCHUNKS (M_TOTAL * DIM / 8)        // 524288
#define WCHUNKS (3 * DIM * DIM / 8)        // 24576
__global__ __launch_bounds__(256) void prep_kernel(
    const float* __restrict__ x,
    const float* __restrict__ Wq, const float* __restrict__ Wk, const float* __restrict__ Wv)
{
    int idx = blockIdx.x * blockDim.x + threadIdx.x;
    if (idx < S_LEN) {
        float s0, c0, s1, c1;
        sincospif((float)(idx % 24) * (1.0f / 12.0f), &s0, &c0);
        sincospif((float)(idx % 720) * (1.0f / 360.0f), &s1, &c1);
        g_cs[idx] = make_float4(c0, s0, c1, s1);
    }
    const float* src; __half* dst; int e;
    if (idx < XCHUNKS) {
        src = x; dst = g_xh; e = idx * 8;
    } else {
        int widx = idx - XCHUNKS;
        if (widx >= WCHUNKS) return;
        int we = widx * 8;
        int z = we >> 16;                   // 65536 = DIM*DIM
        src = (z == 0) ? Wq : (z == 1) ? Wk : Wv;
        dst = g_Wh + (z << 16);
        e = we & 65535;
    }
    float4 v0 = *(const float4*)(src + e);
    float4 v1 = *(const float4*)(src + e + 4);
    __half2* d2 = (__half2*)(dst + e);
    d2[0] = __floats2half2_rn(v0.x, v0.y);
    d2[1] = __floats2half2_rn(v0.z, v0.w);
    d2[2] = __floats2half2_rn(v1.x, v1.y);
    d2[3] = __floats2half2_rn(v1.z, v1.w);
}

// ---------------------------------------------------------------------------
// QKV projection on HMMA: 64-row CTAs, 128 threads, 2 CTAs/SM co-resident.
// z=0: Q (scaled log2e/16) -> g_Qh ; z=1: K -> g_Kh ; z=2: V -> g_VTh (transposed).
// ---------------------------------------------------------------------------
#define QK_BIAS 0                 // 256 floats = 512 halves
#define QK_X0 512                 // 64*72 halves, x2 buffers
#define QK_W0 9728                // 256*72 halves, x2 buffers
#define QK_SMEM (46592 * 2)       // 93,184 B
#define XBUF_H 4608
#define WBUF_H 18432
#define P_TR 266                  // transpose staging pitch (over W buffers)

__global__ __launch_bounds__(128, 2) void qkv_kernel(
    const float* __restrict__ bq, const float* __restrict__ bk, const float* __restrict__ bv)
{
    extern __shared__ __align__(16) __half smq[];
    int z = blockIdx.z;
    const float* bias = (z == 0) ? bq : (z == 1) ? bk : bv;
    const __half* Wsrc = g_Wh + (z << 16);

    uint32_t uS = smem_u32(smq);
    int tid = threadIdx.x;
    int lane = tid & 31, wid = tid >> 5;
    int g = lane >> 2, tig = lane & 3;
    int l7 = lane & 7, bit3 = (lane >> 3) & 1, bit4 = (lane >> 4) & 1;
    int warp_m = wid * 16;                  // 4 warps x 16 = 64 rows
    int m0 = blockIdx.x * 64;
    const __half* Xsrc = g_xh + (size_t)m0 * DIM;

    float* biasS = (float*)(smq + QK_BIAS);
    for (int n = tid; n < 256; n += 128) biasS[n] = bias[n];

    uint32_t xa_h = uS + (uint32_t)(QK_X0 + (warp_m + l7 + bit3 * 8) * 72 + bit4 * 8) * 2;
    uint32_t wb_h = uS + (uint32_t)(QK_W0 + (l7 + bit4 * 8) * 72 + bit3 * 8) * 2;

    // async chunk loader: x 64x64, W 256x64 (fp16, padded pitch 72)
    auto load_chunk = [&](int c) {
        int k0 = c * 64;
        uint32_t xoff = uS + (QK_X0 + (c & 1) * XBUF_H) * 2;
        uint32_t woff = uS + (QK_W0 + (c & 1) * WBUF_H) * 2;
        #pragma unroll
        for (int f = tid; f < 512; f += 128) {        // x: 64 rows x 8 chunks
            int r = f >> 3, cc = f & 7;
            CP16(xoff + (uint32_t)r * 144 + cc * 16, Xsrc + (size_t)r * DIM + k0 + cc * 8);
        }
        #pragma unroll
        for (int f = tid; f < 2048; f += 128) {       // W: 256 rows x 8 chunks
            int r = f >> 3, cc = f & 7;
            CP16(woff + (uint32_t)r * 144 + cc * 16, Wsrc + (size_t)r * DIM + k0 + cc * 8);
        }
    };

    load_chunk(0);
    CP_COMMIT();

    float y[128];
    #pragma unroll
    for (int i = 0; i < 128; i++) y[i] = 0.0f;

    #pragma unroll 1
    for (int c = 0; c < 4; c++) {
        CP_WAIT0();
        __syncthreads();
        if (c + 1 < 4) { load_chunk(c + 1); CP_COMMIT(); }

        uint32_t xbuf = (uint32_t)(c & 1) * (XBUF_H * 2);
        uint32_t wbuf = (uint32_t)(c & 1) * (WBUF_H * 2);
        #pragma unroll
        for (int ks = 0; ks < 4; ks++) {
            uint32_t ah[4];
            ldsm4(ah[0], ah[1], ah[2], ah[3], xa_h + xbuf + ks * 32);
            #pragma unroll
            for (int j2 = 0; j2 < 16; j2++) {
                uint32_t bh[4];
                ldsm4(bh[0], bh[1], bh[2], bh[3], wb_h + wbuf + j2 * 2304 + ks * 32);
                mma16816(&y[(j2 * 2) * 4],     ah, &bh[0]);
                mma16816(&y[(j2 * 2 + 1) * 4], ah, &bh[2]);
            }
        }
    }

    if (z < 2) {
        float scale = (z == 0) ? (LOG2E / 16.0f) : 1.0f;
        __half* dst = ((z == 0) ? g_Qh : g_Kh);
        __half* rowA = dst + (size_t)(m0 + warp_m + g) * DIM;
        __half* rowB = rowA + 8 * DIM;
        #pragma unroll
        for (int jt = 0; jt < 32; jt++) {
            int n = jt * 8 + tig * 2;
            *(__half2*)(rowA + n) = __floats2half2_rn((y[jt*4+0] + biasS[n])   * scale,
                                                      (y[jt*4+1] + biasS[n+1]) * scale);
            *(__half2*)(rowB + n) = __floats2half2_rn((y[jt*4+2] + biasS[n])   * scale,
                                                      (y[jt*4+3] + biasS[n+1]) * scale);
        }
    } else {
        __syncthreads();
        __half* tr = smq + QK_W0;    // staging over W buffers (36864 halves >= 64*266)
        #pragma unroll
        for (int jt = 0; jt < 32; jt++) {
            int n = jt * 8 + tig * 2;
            *(__half2*)&tr[(warp_m + g)     * P_TR + n] =
                __floats2half2_rn(y[jt*4+0] + biasS[n], y[jt*4+1] + biasS[n+1]);
            *(__half2*)&tr[(warp_m + g + 8) * P_TR + n] =
                __floats2half2_rn(y[jt*4+2] + biasS[n], y[jt*4+3] + biasS[n+1]);
        }
        __syncthreads();
        int b_ = m0 >> 12, s_base = m0 & (S_LEN - 1);
        int s = tid & 63, dh = tid >> 6;             // dh in 0..1
        __half* vt = g_VTh + (size_t)b_ * DIM * S_LEN + s_base + s;
        #pragma unroll 8
        for (int i = 0; i < 128; i++) {
            int d = i * 2 + dh;
            vt[(size_t)d * S_LEN] = tr[s * P_TR + d];
        }
    }
}

// ---------------------------------------------------------------------------
// Flash attention on HMMA (proven structure, untouched).
// ---------------------------------------------------------------------------
#define A_Q   0                  // 128 x 264
#define A_K0  33792              // 64 x 264  (x2 buffers)
#define A_V0  67584              // 256 x 72  (x2 buffers)
#define A_CS0 104448             // 64 float4 = 512 halves  (x2 buffers)
#define ATTN_SMEM (105472 * 2)   // 210,944 B
#define KBUF_B (16896 * 2)
#define VBUF_B (18432 * 2)

__global__ __launch_bounds__(256, 1) void attn_kernel(
    const float* __restrict__ beta, float* __restrict__ out)
{
    extern __shared__ __align__(16) __half smh[];
    uint32_t uS = smem_u32(smh);

    int tid = threadIdx.x;
    int lane = tid & 31, wid = tid >> 5;
    int g = lane >> 2, tig = lane & 3;
    int l7 = lane & 7, bit3 = (lane >> 3) & 1, bit4 = (lane >> 4) & 1;
    int warp_m = wid * 16;
    int b = blockIdx.y;
    int q0 = blockIdx.x * 128;

    const __half* Qg = g_Qh + ((size_t)b * S_LEN + q0) * DIM;
    const __half* Kg = g_Kh + (size_t)b * S_LEN * DIM;
    const __half* Vg = g_VTh + (size_t)b * DIM * S_LEN;

    uint32_t qa_lane = uS + (uint32_t)(A_Q + (warp_m + l7 + bit3 * 8) * 264 + bit4 * 8) * 2;
    uint32_t kb_lane = uS + (uint32_t)(A_K0 + (l7 + bit4 * 8) * 264 + bit3 * 8) * 2;
    uint32_t vb_lane = uS + (uint32_t)(A_V0 + (l7 + bit4 * 8) * 72 + bit3 * 8) * 2;

    auto load_kv = [&](int it) {
        int t0 = it * KVT;
        uint32_t koff = uS + A_K0 * 2 + (it & 1) * KBUF_B;
        uint32_t voff = uS + A_V0 * 2 + (it & 1) * VBUF_B;
        const __half* Ksrc = Kg + (size_t)t0 * DIM;
        const __half* Vsrc = Vg + t0;
        #pragma unroll
        for (int f = tid; f < 2048; f += 256) {
            int r = f >> 5, c = f & 31;
            CP16(koff + (uint32_t)r * 528 + c * 16, Ksrc + (size_t)r * DIM + c * 8);
        }
        #pragma unroll
        for (int f = tid; f < 2048; f += 256) {
            int r = f >> 3, c = f & 7;
            CP16(voff + (uint32_t)r * 144 + c * 16, Vsrc + (size_t)r * S_LEN + c * 8);
        }
        if (tid < KVT) {
            uint32_t csoff = uS + A_CS0 * 2 + (it & 1) * 1024;
            CP16(csoff + tid * 16, (const char*)(g_cs + t0 + tid));
        }
    };

    #pragma unroll
    for (int f = tid; f < 4096; f += 256) {
        int r = f >> 5, c = f & 31;
        CP16(uS + A_Q * 2 + (uint32_t)r * 528 + c * 16, Qg + (size_t)r * DIM + c * 8);
    }
    load_kv(0);
    CP_COMMIT();

    float b0 = beta[0] * LOG2E, b1 = beta[1] * LOG2E;
    float cra[4], crb[4];
    {
        float4 ca = g_cs[q0 + warp_m + g];
        float4 cb = g_cs[q0 + warp_m + g + 8];
        cra[0] = b0 * ca.x; cra[1] = b0 * ca.y; cra[2] = b1 * ca.z; cra[3] = b1 * ca.w;
        crb[0] = b0 * cb.x; crb[1] = b0 * cb.y; crb[2] = b1 * cb.z; crb[3] = b1 * cb.w;
    }

    float o[128];
    #pragma unroll
    for (int i = 0; i < 128; i++) o[i] = 0.0f;
    float l0 = 0.0f, l1 = 0.0f;

    #pragma unroll 1
    for (int it = 0; it < NITER; it++) {
        CP_WAIT0();
        __syncthreads();
        if (it + 1 < NITER) { load_kv(it + 1); CP_COMMIT(); }

        uint32_t kbuf = (it & 1) * KBUF_B, vbuf = (it & 1) * VBUF_B;
        const float4* csS = (const float4*)(smh + A_CS0 + (it & 1) * 512);

        float s[32];
        #pragma unroll
        for (int i = 0; i < 32; i++) s[i] = 0.0f;
        #pragma unroll
        for (int ks = 0; ks < 16; ks++) {
            uint32_t a[4];
            ldsm4(a[0], a[1], a[2], a[3], qa_lane + ks * 32);
            #pragma unroll
            for (int j2 = 0; j2 < 4; j2++) {
                uint32_t bb[4];
                ldsm4(bb[0], bb[1], bb[2], bb[3], kb_lane + kbuf + j2 * 8448 + ks * 32);
                mma16816(&s[(j2 * 2) * 4], a, &bb[0]);
                mma16816(&s[(j2 * 2 + 1) * 4], a, &bb[2]);
            }
        }

        #pragma unroll
        for (int ks = 0; ks < 4; ks++) {
            uint32_t ph[4];
            #pragma unroll
            for (int jj = 0; jj < 2; jj++) {
                int j = ks * 2 + jj;
                float4 k0 = csS[j * 8 + tig * 2];
                float4 k1 = csS[j * 8 + tig * 2 + 1];
                float e0 = ex2f(s[j*4+0] + cra[0]*k0.x + cra[1]*k0.y + cra[2]*k0.z + cra[3]*k0.w);
                float e1 = ex2f(s[j*4+1] + cra[0]*k1.x + cra[1]*k1.y + cra[2]*k1.z + cra[3]*k1.w);
                float e2 = ex2f(s[j*4+2] + crb[0]*k0.x + crb[1]*k0.y + crb[2]*k0.z + crb[3]*k0.w);
                float e3 = ex2f(s[j*4+3] + crb[0]*k1.x + crb[1]*k1.y + crb[2]*k1.z + crb[3]*k1.w);
                l0 += e0 + e1; l1 += e2 + e3;
                ph[jj * 2]     = pk2(e0, e1);
                ph[jj * 2 + 1] = pk2(e2, e3);
            }
            #pragma unroll
            for (int j2 = 0; j2 < 16; j2++) {
                uint32_t vh[4];
                ldsm4(vh[0], vh[1], vh[2], vh[3], vb_lane + vbuf + j2 * 2304 + ks * 32);
                mma16816(&o[(j2 * 2) * 4],     ph, &vh[0]);
                mma16816(&o[(j2 * 2 + 1) * 4], ph, &vh[2]);
            }
        }
    }

    l0 += __shfl_xor_sync(0xffffffffu, l0, 1);
    l0 += __shfl_xor_sync(0xffffffffu, l0, 2);
    l1 += __shfl_xor_sync(0xffffffffu, l1, 1);
    l1 += __shfl_xor_sync(0xffffffffu, l1, 2);
    float inv0 = 1.0f / l0, inv1 = 1.0f / l1;

    float* outA = out + ((size_t)b * S_LEN + q0 + warp_m + g) * DIM;
    float* outB = outA + 8 * DIM;
    #pragma unroll
    for (int jt = 0; jt < 32; jt++) {
        *(float2*)(outA + jt * 8 + tig * 2) = make_float2(o[jt*4+0] * inv0, o[jt*4+1] * inv0);
        *(float2*)(outB + jt * 8 + tig * 2) = make_float2(o[jt*4+2] * inv1, o[jt*4+3] * inv1);
    }
}

// ---------------------------------------------------------------------------
extern "C" void kernel_launch(void* const* d_in, const int* in_sizes, int n_in,
                              void* d_out, int out_size)
{
    const float* x    = (const float*)d_in[0];
    const float* Wq   = (const float*)d_in[1];
    const float* bq   = (const float*)d_in[2];
    const float* Wk   = (const float*)d_in[3];
    const float* bk   = (const float*)d_in[4];
    const float* Wv   = (const float*)d_in[5];
    const float* bv   = (const float*)d_in[6];
    const float* beta = (const float*)d_in[7];
    float* out = (float*)d_out;
    (void)in_sizes; (void)n_in; (void)out_size;

    cudaFuncSetAttribute(qkv_kernel,  cudaFuncAttributeMaxDynamicSharedMemorySize, QK_SMEM);
    cudaFuncSetAttribute(attn_kernel, cudaFuncAttributeMaxDynamicSharedMemorySize, ATTN_SMEM);

    prep_kernel<<<(XCHUNKS + WCHUNKS + 255) / 256, 256>>>(x, Wq, Wk, Wv);
    qkv_kernel<<<dim3(M_TOTAL / 64, 1, 3), 128, QK_SMEM>>>(bq, bk, bv);
    attn_kernel<<<dim3(S_LEN / 128, NBATCH), 256, ATTN_SMEM>>>(beta, out);
}

// round 15
// speedup vs baseline: 1.1787x; 1.0808x over previous
#include <cuda_runtime.h>
#include <cuda_fp16.h>
#include <math.h>
#include <stdint.h>

#define S_LEN 4096
#define NBATCH 4
#define DIM 256
#define M_TOTAL (NBATCH * S_LEN)
#define KVT 64
#define NITER (S_LEN / KVT)
#define SPLIT_IT 56                       // A piece: [0,56), B piece: [56,64)
#define LOG2E 1.4426950408889634f

// ---------------- scratch globals ----------------
__device__ __half g_xh[M_TOTAL * DIM];
__device__ __half g_Wh[3 * DIM * DIM];
__device__ __half g_Qh[M_TOTAL * DIM];              // pre-scaled log2e/16
__device__ __half g_Kh[M_TOTAL * DIM];
__device__ __half g_VTh[NBATCH * DIM * S_LEN];      // [b][d][s]
__device__ float4 g_cs[S_LEN];
__device__ float g_oB[M_TOTAL * DIM];               // B-piece unnormalized O
__device__ float g_lA[M_TOTAL];                     // A-piece softmax denom
__device__ float g_lB[M_TOTAL];                     // B-piece softmax denom

// ---------------- low-level helpers ----------------
__device__ __forceinline__ uint32_t smem_u32(const void* p) {
    uint32_t a;
    asm("{ .reg .u64 t; cvta.to.shared.u64 t, %1; cvt.u32.u64 %0, t; }" : "=r"(a) : "l"(p));
    return a;
}
__device__ __forceinline__ void ldsm4(uint32_t& r0, uint32_t& r1, uint32_t& r2, uint32_t& r3,
                                      uint32_t addr) {
    asm volatile("ldmatrix.sync.aligned.m8n8.x4.shared.b16 {%0,%1,%2,%3}, [%4];"
                 : "=r"(r0), "=r"(r1), "=r"(r2), "=r"(r3) : "r"(addr));
}
__device__ __forceinline__ void mma16816(float* d, const uint32_t* a, const uint32_t* b) {
    asm volatile("mma.sync.aligned.m16n8k16.row.col.f32.f16.f16.f32 "
                 "{%0,%1,%2,%3}, {%4,%5,%6,%7}, {%8,%9}, {%0,%1,%2,%3};"
                 : "+f"(d[0]), "+f"(d[1]), "+f"(d[2]), "+f"(d[3])
                 : "r"(a[0]), "r"(a[1]), "r"(a[2]), "r"(a[3]), "r"(b[0]), "r"(b[1]));
}
__device__ __forceinline__ uint32_t pk2(float x, float y) {
    __half2 h = __floats2half2_rn(x, y);
    return reinterpret_cast<uint32_t&>(h);
}
__device__ __forceinline__ float ex2f(float x) {
    float y; asm("ex2.approx.ftz.f32 %0, %1;" : "=f"(y) : "f"(x)); return y;
}
#define CP16(dst, src) \
    asm volatile("cp.async.cg.shared.global [%0], [%1], 16;" :: "r"(dst), "l"(src))
#define CP_COMMIT() asm volatile("cp.async.commit_group;" ::: "memory")
#define CP_WAIT0()  asm volatile("cp.async.wait_group 0;" ::: "memory")

// ---------------------------------------------------------------------------
// prep: cos/sin table + fp32->fp16 conversion of x and all W (one launch)
// ---------------------------------------------------------------------------
#define XCHUNKS (M_TOTAL * DIM / 8)        // 524288
#define WCHUNKS (3 * DIM * DIM / 8)        // 24576
__global__ __launch_bounds__(256) void prep_kernel(
    const float* __restrict__ x,
    const float* __restrict__ Wq, const float* __restrict__ Wk, const float* __restrict__ Wv)
{
    int idx = blockIdx.x * blockDim.x + threadIdx.x;
    if (idx < S_LEN) {
        float s0, c0, s1, c1;
        sincospif((float)(idx % 24) * (1.0f / 12.0f), &s0, &c0);
        sincospif((float)(idx % 720) * (1.0f / 360.0f), &s1, &c1);
        g_cs[idx] = make_float4(c0, s0, c1, s1);
    }
    const float* src; __half* dst; int e;
    if (idx < XCHUNKS) {
        src = x; dst = g_xh; e = idx * 8;
    } else {
        int widx = idx - XCHUNKS;
        if (widx >= WCHUNKS) return;
        int we = widx * 8;
        int z = we >> 16;
        src = (z == 0) ? Wq : (z == 1) ? Wk : Wv;
        dst = g_Wh + (z << 16);
        e = we & 65535;
    }
    float4 v0 = *(const float4*)(src + e);
    float4 v1 = *(const float4*)(src + e + 4);
    __half2 h0 = __floats2half2_rn(v0.x, v0.y);
    __half2 h1 = __floats2half2_rn(v0.z, v0.w);
    __half2 h2 = __floats2half2_rn(v1.x, v1.y);
    __half2 h3 = __floats2half2_rn(v1.z, v1.w);
    uint4 pk = make_uint4(reinterpret_cast<uint32_t&>(h0), reinterpret_cast<uint32_t&>(h1),
                          reinterpret_cast<uint32_t&>(h2), reinterpret_cast<uint32_t&>(h3));
    *(uint4*)(dst + e) = pk;
}

// ---------------------------------------------------------------------------
// QKV projection on HMMA: 64-row CTAs, 128 threads, 2 CTAs/SM co-resident.
// ---------------------------------------------------------------------------
#define QK_BIAS 0
#define QK_X0 512
#define QK_W0 9728
#define QK_SMEM (46592 * 2)
#define XBUF_H 4608
#define WBUF_H 18432
#define P_TR 266

__global__ __launch_bounds__(128, 2) void qkv_kernel(
    const float* __restrict__ bq, const float* __restrict__ bk, const float* __restrict__ bv)
{
    extern __shared__ __align__(16) __half smq[];
    int z = blockIdx.z;
    const float* bias = (z == 0) ? bq : (z == 1) ? bk : bv;
    const __half* Wsrc = g_Wh + (z << 16);

    uint32_t uS = smem_u32(smq);
    int tid = threadIdx.x;
    int lane = tid & 31, wid = tid >> 5;
    int g = lane >> 2, tig = lane & 3;
    int l7 = lane & 7, bit3 = (lane >> 3) & 1, bit4 = (lane >> 4) & 1;
    int warp_m = wid * 16;
    int m0 = blockIdx.x * 64;
    const __half* Xsrc = g_xh + (size_t)m0 * DIM;

    float* biasS = (float*)(smq + QK_BIAS);
    for (int n = tid; n < 256; n += 128) biasS[n] = bias[n];

    uint32_t xa_h = uS + (uint32_t)(QK_X0 + (warp_m + l7 + bit3 * 8) * 72 + bit4 * 8) * 2;
    uint32_t wb_h = uS + (uint32_t)(QK_W0 + (l7 + bit4 * 8) * 72 + bit3 * 8) * 2;

    auto load_chunk = [&](int c) {
        int k0 = c * 64;
        uint32_t xoff = uS + (QK_X0 + (c & 1) * XBUF_H) * 2;
        uint32_t woff = uS + (QK_W0 + (c & 1) * WBUF_H) * 2;
        #pragma unroll
        for (int f = tid; f < 512; f += 128) {
            int r = f >> 3, cc = f & 7;
            CP16(xoff + (uint32_t)r * 144 + cc * 16, Xsrc + (size_t)r * DIM + k0 + cc * 8);
        }
        #pragma unroll
        for (int f = tid; f < 2048; f += 128) {
            int r = f >> 3, cc = f & 7;
            CP16(woff + (uint32_t)r * 144 + cc * 16, Wsrc + (size_t)r * DIM + k0 + cc * 8);
        }
    };

    load_chunk(0);
    CP_COMMIT();

    float y[128];
    #pragma unroll
    for (int i = 0; i < 128; i++) y[i] = 0.0f;

    #pragma unroll 1
    for (int c = 0; c < 4; c++) {
        CP_WAIT0();
        __syncthreads();
        if (c + 1 < 4) { load_chunk(c + 1); CP_COMMIT(); }

        uint32_t xbuf = (uint32_t)(c & 1) * (XBUF_H * 2);
        uint32_t wbuf = (uint32_t)(c & 1) * (WBUF_H * 2);
        #pragma unroll
        for (int ks = 0; ks < 4; ks++) {
            uint32_t ah[4];
            ldsm4(ah[0], ah[1], ah[2], ah[3], xa_h + xbuf + ks * 32);
            #pragma unroll
            for (int j2 = 0; j2 < 16; j2++) {
                uint32_t bh[4];
                ldsm4(bh[0], bh[1], bh[2], bh[3], wb_h + wbuf + j2 * 2304 + ks * 32);
                mma16816(&y[(j2 * 2) * 4],     ah, &bh[0]);
                mma16816(&y[(j2 * 2 + 1) * 4], ah, &bh[2]);
            }
        }
    }

    if (z < 2) {
        float scale = (z == 0) ? (LOG2E / 16.0f) : 1.0f;
        __half* dst = ((z == 0) ? g_Qh : g_Kh);
        __half* rowA = dst + (size_t)(m0 + warp_m + g) * DIM;
        __half* rowB = rowA + 8 * DIM;
        #pragma unroll
        for (int jt = 0; jt < 32; jt++) {
            int n = jt * 8 + tig * 2;
            *(__half2*)(rowA + n) = __floats2half2_rn((y[jt*4+0] + biasS[n])   * scale,
                                                      (y[jt*4+1] + biasS[n+1]) * scale);
            *(__half2*)(rowB + n) = __floats2half2_rn((y[jt*4+2] + biasS[n])   * scale,
                                                      (y[jt*4+3] + biasS[n+1]) * scale);
        }
    } else {
        __syncthreads();
        __half* tr = smq + QK_W0;
        #pragma unroll
        for (int jt = 0; jt < 32; jt++) {
            int n = jt * 8 + tig * 2;
            *(__half2*)&tr[(warp_m + g)     * P_TR + n] =
                __floats2half2_rn(y[jt*4+0] + biasS[n], y[jt*4+1] + biasS[n+1]);
            *(__half2*)&tr[(warp_m + g + 8) * P_TR + n] =
                __floats2half2_rn(y[jt*4+2] + biasS[n], y[jt*4+3] + biasS[n+1]);
        }
        __syncthreads();
        int b_ = m0 >> 12, s_base = m0 & (S_LEN - 1);
        int s = tid & 63, dh = tid >> 6;
        __half* vt = g_VTh + (size_t)b_ * DIM * S_LEN + s_base + s;
        #pragma unroll 8
        for (int i = 0; i < 128; i++) {
            int d = i * 2 + dh;
            vt[(size_t)d * S_LEN] = tr[s * P_TR + d];
        }
    }
}

// ---------------------------------------------------------------------------
// Flash attention, kv-split into A [0,56) and B [56,64) pieces per tile.
// A pieces (blocks 0..127) write unnormalized O into out + l into g_lA.
// B pieces (blocks 128..255) write into g_oB / g_lB. combine_kernel finishes.
// ---------------------------------------------------------------------------
#define A_Q   0
#define A_K0  33792
#define A_V0  67584
#define A_CS0 104448
#define ATTN_SMEM (105472 * 2)
#define KBUF_B (16896 * 2)
#define VBUF_B (18432 * 2)

__global__ __launch_bounds__(256, 1) void attn_kernel(const float* __restrict__ beta,
                                                      float* __restrict__ out)
{
    extern __shared__ __align__(16) __half smh[];
    uint32_t uS = smem_u32(smh);

    int tid = threadIdx.x;
    int lane = tid & 31, wid = tid >> 5;
    int g = lane >> 2, tig = lane & 3;
    int l7 = lane & 7, bit3 = (lane >> 3) & 1, bit4 = (lane >> 4) & 1;
    int warp_m = wid * 16;

    int piece = blockIdx.x;
    int isA = (piece < 128);
    int tile = piece & 127;
    int b = tile >> 5;
    int q0 = (tile & 31) * 128;
    int it0 = isA ? 0 : SPLIT_IT;
    int it1 = isA ? SPLIT_IT : NITER;

    const __half* Qg = g_Qh + ((size_t)b * S_LEN + q0) * DIM;
    const __half* Kg = g_Kh + (size_t)b * S_LEN * DIM;
    const __half* Vg = g_VTh + (size_t)b * DIM * S_LEN;

    uint32_t qa_lane = uS + (uint32_t)(A_Q + (warp_m + l7 + bit3 * 8) * 264 + bit4 * 8) * 2;
    uint32_t kb_lane = uS + (uint32_t)(A_K0 + (l7 + bit4 * 8) * 264 + bit3 * 8) * 2;
    uint32_t vb_lane = uS + (uint32_t)(A_V0 + (l7 + bit4 * 8) * 72 + bit3 * 8) * 2;

    auto load_kv = [&](int it) {
        int t0 = it * KVT;
        uint32_t koff = uS + A_K0 * 2 + (it & 1) * KBUF_B;
        uint32_t voff = uS + A_V0 * 2 + (it & 1) * VBUF_B;
        const __half* Ksrc = Kg + (size_t)t0 * DIM;
        const __half* Vsrc = Vg + t0;
        #pragma unroll
        for (int f = tid; f < 2048; f += 256) {
            int r = f >> 5, c = f & 31;
            CP16(koff + (uint32_t)r * 528 + c * 16, Ksrc + (size_t)r * DIM + c * 8);
        }
        #pragma unroll
        for (int f = tid; f < 2048; f += 256) {
            int r = f >> 3, c = f & 7;
            CP16(voff + (uint32_t)r * 144 + c * 16, Vsrc + (size_t)r * S_LEN + c * 8);
        }
        if (tid < KVT) {
            uint32_t csoff = uS + A_CS0 * 2 + (it & 1) * 1024;
            CP16(csoff + tid * 16, (const char*)(g_cs + t0 + tid));
        }
    };

    #pragma unroll
    for (int f = tid; f < 4096; f += 256) {
        int r = f >> 5, c = f & 31;
        CP16(uS + A_Q * 2 + (uint32_t)r * 528 + c * 16, Qg + (size_t)r * DIM + c * 8);
    }
    load_kv(it0);
    CP_COMMIT();

    float b0 = beta[0] * LOG2E, b1 = beta[1] * LOG2E;
    float cra[4], crb[4];
    {
        float4 ca = g_cs[q0 + warp_m + g];
        float4 cb = g_cs[q0 + warp_m + g + 8];
        cra[0] = b0 * ca.x; cra[1] = b0 * ca.y; cra[2] = b1 * ca.z; cra[3] = b1 * ca.w;
        crb[0] = b0 * cb.x; crb[1] = b0 * cb.y; crb[2] = b1 * cb.z; crb[3] = b1 * cb.w;
    }

    float o[128];
    #pragma unroll
    for (int i = 0; i < 128; i++) o[i] = 0.0f;
    float l0 = 0.0f, l1 = 0.0f;

    #pragma unroll 1
    for (int it = it0; it < it1; it++) {
        CP_WAIT0();
        __syncthreads();
        if (it + 1 < it1) { load_kv(it + 1); CP_COMMIT(); }

        uint32_t kbuf = (it & 1) * KBUF_B, vbuf = (it & 1) * VBUF_B;
        const float4* csS = (const float4*)(smh + A_CS0 + (it & 1) * 512);

        float s[32];
        #pragma unroll
        for (int i = 0; i < 32; i++) s[i] = 0.0f;
        #pragma unroll
        for (int ks = 0; ks < 16; ks++) {
            uint32_t a[4];
            ldsm4(a[0], a[1], a[2], a[3], qa_lane + ks * 32);
            #pragma unroll
            for (int j2 = 0; j2 < 4; j2++) {
                uint32_t bb[4];
                ldsm4(bb[0], bb[1], bb[2], bb[3], kb_lane + kbuf + j2 * 8448 + ks * 32);
                mma16816(&s[(j2 * 2) * 4], a, &bb[0]);
                mma16816(&s[(j2 * 2 + 1) * 4], a, &bb[2]);
            }
        }

        #pragma unroll
        for (int ks = 0; ks < 4; ks++) {
            uint32_t ph[4];
            #pragma unroll
            for (int jj = 0; jj < 2; jj++) {
                int j = ks * 2 + jj;
                float4 k0 = csS[j * 8 + tig * 2];
                float4 k1 = csS[j * 8 + tig * 2 + 1];
                float e0 = ex2f(s[j*4+0] + cra[0]*k0.x + cra[1]*k0.y + cra[2]*k0.z + cra[3]*k0.w);
                float e1 = ex2f(s[j*4+1] + cra[0]*k1.x + cra[1]*k1.y + cra[2]*k1.z + cra[3]*k1.w);
                float e2 = ex2f(s[j*4+2] + crb[0]*k0.x + crb[1]*k0.y + crb[2]*k0.z + crb[3]*k0.w);
                float e3 = ex2f(s[j*4+3] + crb[0]*k1.x + crb[1]*k1.y + crb[2]*k1.z + crb[3]*k1.w);
                l0 += e0 + e1; l1 += e2 + e3;
                ph[jj * 2]     = pk2(e0, e1);
                ph[jj * 2 + 1] = pk2(e2, e3);
            }
            #pragma unroll
            for (int j2 = 0; j2 < 16; j2++) {
                uint32_t vh[4];
                ldsm4(vh[0], vh[1], vh[2], vh[3], vb_lane + vbuf + j2 * 2304 + ks * 32);
                mma16816(&o[(j2 * 2) * 4],     ph, &vh[0]);
                mma16816(&o[(j2 * 2 + 1) * 4], ph, &vh[2]);
            }
        }
    }

    // ---- epilogue: quad-reduce l, write UNNORMALIZED o + l ----
    l0 += __shfl_xor_sync(0xffffffffu, l0, 1);
    l0 += __shfl_xor_sync(0xffffffffu, l0, 2);
    l1 += __shfl_xor_sync(0xffffffffu, l1, 1);
    l1 += __shfl_xor_sync(0xffffffffu, l1, 2);

    size_t rowA = (size_t)b * S_LEN + q0 + warp_m + g;
    float* dst = (isA ? out : g_oB);
    float* ldst = (isA ? g_lA : g_lB);
    if (tig == 0) { ldst[rowA] = l0; ldst[rowA + 8] = l1; }
    float* outA = dst + rowA * DIM;
    float* outB = outA + 8 * DIM;
    #pragma unroll
    for (int jt = 0; jt < 32; jt++) {
        *(float2*)(outA + jt * 8 + tig * 2) = make_float2(o[jt*4+0], o[jt*4+1]);
        *(float2*)(outB + jt * 8 + tig * 2) = make_float2(o[jt*4+2], o[jt*4+3]);
    }
}

// ---------------------------------------------------------------------------
// combine: out = (out + oB) / (lA + lB), float4-vectorized
// ---------------------------------------------------------------------------
__global__ __launch_bounds__(256) void combine_kernel(float* __restrict__ out)
{
    int idx4 = blockIdx.x * blockDim.x + threadIdx.x;   // over M_TOTAL*DIM/4
    int row = idx4 >> 6;                                 // 64 float4 per row
    float inv = 1.0f / (g_lA[row] + g_lB[row]);
    float4 a = ((const float4*)out)[idx4];
    float4 bv = ((const float4*)g_oB)[idx4];
    a.x = (a.x + bv.x) * inv;
    a.y = (a.y + bv.y) * inv;
    a.z = (a.z + bv.z) * inv;
    a.w = (a.w + bv.w) * inv;
    ((float4*)out)[idx4] = a;
}

// ---------------------------------------------------------------------------
extern "C" void kernel_launch(void* const* d_in, const int* in_sizes, int n_in,
                              void* d_out, int out_size)
{
    const float* x    = (const float*)d_in[0];
    const float* Wq   = (const float*)d_in[1];
    const float* bq   = (const float*)d_in[2];
    const float* Wk   = (const float*)d_in[3];
    const float* bk   = (const float*)d_in[4];
    const float* Wv   = (const float*)d_in[5];
    const float* bv   = (const float*)d_in[6];
    const float* beta = (const float*)d_in[7];
    float* out = (float*)d_out;
    (void)in_sizes; (void)n_in; (void)out_size;

    cudaFuncSetAttribute(qkv_kernel,  cudaFuncAttributeMaxDynamicSharedMemorySize, QK_SMEM);
    cudaFuncSetAttribute(attn_kernel, cudaFuncAttributeMaxDynamicSharedMemorySize, ATTN_SMEM);

    prep_kernel<<<(XCHUNKS + WCHUNKS + 255) / 256, 256>>>(x, Wq, Wk, Wv);
    qkv_kernel<<<dim3(M_TOTAL / 64, 1, 3), 128, QK_SMEM>>>(bq, bk, bv);
    attn_kernel<<<256, 256, ATTN_SMEM>>>(beta, out);
    combine_kernel<<<M_TOTAL * DIM / 4 / 256, 256>>>(out);
}